// round 5
// baseline (speedup 1.0000x reference)
#include <cuda_runtime.h>
#include <cstdint>

// YOLOv7 P3 head: B=16, A=3, C=85/anchor, H=W=80, stride 8.
// Input:  [b, a, ch(85), h, w]   Output: [b, a*h*w, 85]
//
// Block = 2 tiles x 64 positions of one (b,a), double-buffered smem.
// Tile t: warps load/transform into sbuf[t] (conflict-free scatter into
// output layout), per-half named barrier, TMA bulk store committed WITHOUT
// waiting -> tile 1 compute overlaps tile 0 write-back. One wait at the end.

#define B_       16
#define A_       3
#define C_       85
#define W_       80
#define HW_      6400
#define TILE_    64
#define THREADS_ 256
#define HALF_BYTES_ (32 * C_ * 4)   // 10880

__device__ __forceinline__ float sigm(float x) {
    float t;
    const float h = 0.5f * x;
    asm("tanh.approx.f32 %0, %1;" : "=f"(t) : "f"(h));   // 1 MUFU
    return fmaf(0.5f, t, 0.5f);
}

__global__ __launch_bounds__(THREADS_)
void yolo_head_kernel(const float* __restrict__ in,
                      const float* __restrict__ anchors,
                      float* __restrict__ out)
{
    __shared__ alignas(128) float sbuf[2][TILE_ * C_];   // 2 x 21760 B

    const int bid   = blockIdx.x;                 // 0..2399
    const int ba    = bid / 50;                   // b*A + a  (2 tiles -> /50)
    const int tile2 = (bid - ba * 50) * 2;        // first of the 2 tiles
    const int a     = ba % A_;

    const float aw = __ldg(&anchors[a * 2 + 0]);
    const float ah = __ldg(&anchors[a * 2 + 1]);

    const int tid  = threadIdx.x;
    const int w    = tid >> 5;
    const int lane = tid & 31;
    const int c    = lane >> 3;              // 0..3
    const int qq   = lane & 7;               // 0..7
    const int s    = w & 1;                  // position half
    const int g0   = w >> 1;                 // 0..3
    const int p    = (s * 8 + qq) * 4;       // local position base 0..60
    const int ch0  = g0 * 4 + c;             // 0..15
    const bool tailValid = (ch0 <= 4);

    const float* baBase = in + (size_t)ba * (C_ * HW_) + (size_t)ch0 * HW_ + p;

    #pragma unroll
    for (int t = 0; t < 2; t++) {
        const int  pos0 = (tile2 + t) * TILE_;
        const float* tptr = baBase + pos0;
        float* sb = sbuf[t];

        // ---- all loads upfront: ch = ch0 + 16k, k=0..5 (k=5 iff ch0<=4)
        float4 r[6];
        #pragma unroll
        for (int k = 0; k < 5; k++)
            r[k] = __ldcs(reinterpret_cast<const float4*>(tptr + (size_t)k * (16 * HW_)));
        if (tailValid)
            r[5] = __ldcs(reinterpret_cast<const float4*>(tptr + (size_t)5 * (16 * HW_)));

        float vv[4];
        #pragma unroll
        for (int k = 0; k < 6; k++) {
            if (k == 5 && !tailValid) break;
            const int ch = ch0 + 16 * k;
            vv[0] = r[k].x; vv[1] = r[k].y; vv[2] = r[k].z; vv[3] = r[k].w;

            if (k == 0 && ch < 4) {          // only warps 0,1 (g0==0)
                if (ch == 0) {
                    const int gp = pos0 + p;
                    #pragma unroll
                    for (int j = 0; j < 4; j++)
                        vv[j] = (sigm(vv[j]) + (float)((gp + j) % W_)) * 8.0f;
                } else if (ch == 1) {
                    const int gp = pos0 + p;
                    #pragma unroll
                    for (int j = 0; j < 4; j++)
                        vv[j] = (sigm(vv[j]) + (float)((gp + j) / W_)) * 8.0f;
                } else {
                    const float sc = (ch == 2) ? aw : ah;
                    #pragma unroll
                    for (int j = 0; j < 4; j++) {
                        const float cl = fminf(fmaxf(vv[j], -16.0f), 16.0f);
                        vv[j] = __expf(cl) * sc;
                    }
                }
            } else {
                #pragma unroll
                for (int j = 0; j < 4; j++) vv[j] = sigm(vv[j]);
            }
            // bank = (20*qq + c + const) mod 32 -> all 32 distinct
            #pragma unroll
            for (int j = 0; j < 4; j++) sb[(p + j) * C_ + ch] = vv[j];
        }

        // ---- per-half named barrier (128 threads), then commit TMA store
        if (s == 0) asm volatile("bar.sync 1, 128;" ::: "memory");
        else        asm volatile("bar.sync 2, 128;" ::: "memory");

        if (lane == 0 && w < 2) {            // warp 0 -> half 0, warp 1 -> half 1
            const int half = w;
            float* outBase = out + ((size_t)(ba * HW_ + pos0) + half * 32) * C_;
            const float* src = sb + half * 32 * C_;
            uint32_t saddr;
            asm("{ .reg .u64 tt; cvta.to.shared.u64 tt, %1; cvt.u32.u64 %0, tt; }"
                : "=r"(saddr) : "l"(src));
            asm volatile("fence.proxy.async.shared::cta;" ::: "memory");
            asm volatile("cp.async.bulk.global.shared::cta.bulk_group [%0], [%1], %2;"
                         :: "l"(outBase), "r"(saddr), "r"((uint32_t)HALF_BYTES_)
                         : "memory");
            asm volatile("cp.async.bulk.commit_group;" ::: "memory");
            // no wait here: tile 1 overlaps tile 0 write-back
        }
    }

    // issuing warps drain both committed groups before exit (smem must stay live)
    if (lane == 0 && w < 2)
        asm volatile("cp.async.bulk.wait_group.read 0;" ::: "memory");
}

extern "C" void kernel_launch(void* const* d_in, const int* in_sizes, int n_in,
                              void* d_out, int out_size) {
    const float* in      = (const float*)d_in[0];
    const float* anchors = (const float*)d_in[1];
    float* out           = (float*)d_out;

    const int blocks = B_ * A_ * (HW_ / TILE_) / 2;   // 2400
    yolo_head_kernel<<<blocks, THREADS_>>>(in, anchors, out);
}

// round 6
// speedup vs baseline: 1.1772x; 1.1772x over previous
#include <cuda_runtime.h>
#include <cstdint>

// YOLOv7 P3 head: B=16, A=3, C=85/anchor, H=W=80, stride 8.
// Input:  [b, a, ch(85), h, w]   Output: [b, a*h*w, 85]
//
// R4 structure (64-pos tile, output-layout smem, per-half TMA store) with
// 8 CTAs/SM: __launch_bounds__(256,8) caps regs at 32, so the 6-deep
// prefetch is split into two 3-deep batches (12 regs of load buffer).
//
// Warp w: s = w&1 (position half), g0 = w>>1. Lane: c = lane>>3, qq = lane&7.
// STS bank = (20*qq + c + const) mod 32 -> conflict-free.

#define B_       16
#define A_       3
#define C_       85
#define W_       80
#define HW_      6400
#define TILE_    64
#define THREADS_ 256
#define HALF_BYTES_ (32 * C_ * 4)   // 10880

__device__ __forceinline__ float sigm(float x) {
    float t;
    const float h = 0.5f * x;
    asm("tanh.approx.f32 %0, %1;" : "=f"(t) : "f"(h));   // 1 MUFU
    return fmaf(0.5f, t, 0.5f);
}

__global__ __launch_bounds__(THREADS_, 8)
void yolo_head_kernel(const float* __restrict__ in,
                      const float* __restrict__ anchors,
                      float* __restrict__ out)
{
    __shared__ alignas(128) float sbuf[TILE_ * C_];   // 21760 B

    const int tilesPerBA = HW_ / TILE_;      // 100
    const int bid  = blockIdx.x;
    const int ba   = bid / tilesPerBA;       // b*A + a
    const int tile = bid - ba * tilesPerBA;
    const int pos0 = tile * TILE_;
    const int a    = ba % A_;

    const float aw = __ldg(&anchors[a * 2 + 0]);
    const float ah = __ldg(&anchors[a * 2 + 1]);

    const int tid  = threadIdx.x;
    const int w    = tid >> 5;
    const int lane = tid & 31;
    const int c    = lane >> 3;              // 0..3
    const int qq   = lane & 7;               // 0..7
    const int s    = w & 1;                  // position half
    const int g0   = w >> 1;                 // 0..3
    const int p    = (s * 8 + qq) * 4;       // local position base 0..60
    const int ch0  = g0 * 4 + c;             // 0..15
    const bool tailValid = (ch0 <= 4);       // ch0+80 <= 84

    const float* tptr = in + (size_t)ba * (C_ * HW_) + pos0
                           + (size_t)ch0 * HW_ + p;

    float vv[4];

    // ---- batch 0: k = 0..2  (ch = ch0 + 16k) ----
    {
        float4 r[3];
        #pragma unroll
        for (int k = 0; k < 3; k++)
            r[k] = __ldcs(reinterpret_cast<const float4*>(tptr + (size_t)k * (16 * HW_)));

        #pragma unroll
        for (int k = 0; k < 3; k++) {
            const int ch = ch0 + 16 * k;
            vv[0] = r[k].x; vv[1] = r[k].y; vv[2] = r[k].z; vv[3] = r[k].w;

            if (k == 0 && ch < 4) {          // only warps 0,1 (g0==0), once
                if (ch == 0) {
                    const int gp = pos0 + p;
                    #pragma unroll
                    for (int j = 0; j < 4; j++)
                        vv[j] = (sigm(vv[j]) + (float)((gp + j) % W_)) * 8.0f;
                } else if (ch == 1) {
                    const int gp = pos0 + p;
                    #pragma unroll
                    for (int j = 0; j < 4; j++)
                        vv[j] = (sigm(vv[j]) + (float)((gp + j) / W_)) * 8.0f;
                } else {
                    const float sc = (ch == 2) ? aw : ah;
                    #pragma unroll
                    for (int j = 0; j < 4; j++) {
                        const float cl = fminf(fmaxf(vv[j], -16.0f), 16.0f);
                        vv[j] = __expf(cl) * sc;
                    }
                }
            } else {
                #pragma unroll
                for (int j = 0; j < 4; j++) vv[j] = sigm(vv[j]);
            }
            #pragma unroll
            for (int j = 0; j < 4; j++) sbuf[(p + j) * C_ + ch] = vv[j];
        }
    }

    // ---- batch 1: k = 3..5  (k=5 valid iff ch0 <= 4) ----
    {
        float4 r[3];
        #pragma unroll
        for (int k = 0; k < 2; k++)
            r[k] = __ldcs(reinterpret_cast<const float4*>(tptr + (size_t)(k + 3) * (16 * HW_)));
        if (tailValid)
            r[2] = __ldcs(reinterpret_cast<const float4*>(tptr + (size_t)5 * (16 * HW_)));

        #pragma unroll
        for (int k = 0; k < 3; k++) {
            if (k == 2 && !tailValid) break;
            const int ch = ch0 + 16 * (k + 3);   // >= 48: always generic path
            vv[0] = r[k].x; vv[1] = r[k].y; vv[2] = r[k].z; vv[3] = r[k].w;
            #pragma unroll
            for (int j = 0; j < 4; j++) vv[j] = sigm(vv[j]);
            #pragma unroll
            for (int j = 0; j < 4; j++) sbuf[(p + j) * C_ + ch] = vv[j];
        }
    }

    // ---- per-half named barrier (128 threads each), then TMA half-store
    if (s == 0) asm volatile("bar.sync 1, 128;" ::: "memory");  // warps 0,2,4,6
    else        asm volatile("bar.sync 2, 128;" ::: "memory");  // warps 1,3,5,7

    if (lane == 0 && w < 2) {                // warp 0 -> half 0, warp 1 -> half 1
        const int half = w;                  // == s for w<2
        float* outBase = out + ((size_t)(ba * HW_ + pos0) + half * 32) * C_;
        const float* src = sbuf + half * 32 * C_;
        uint32_t saddr;
        asm("{ .reg .u64 t; cvta.to.shared.u64 t, %1; cvt.u32.u64 %0, t; }"
            : "=r"(saddr) : "l"(src));
        asm volatile("fence.proxy.async.shared::cta;" ::: "memory");
        asm volatile("cp.async.bulk.global.shared::cta.bulk_group [%0], [%1], %2;"
                     :: "l"(outBase), "r"(saddr), "r"((uint32_t)HALF_BYTES_)
                     : "memory");
        asm volatile("cp.async.bulk.commit_group;" ::: "memory");
        asm volatile("cp.async.bulk.wait_group.read 0;" ::: "memory");
    }
}

extern "C" void kernel_launch(void* const* d_in, const int* in_sizes, int n_in,
                              void* d_out, int out_size) {
    const float* in      = (const float*)d_in[0];
    const float* anchors = (const float*)d_in[1];
    float* out           = (float*)d_out;

    const int blocks = B_ * A_ * (HW_ / TILE_);   // 4800
    yolo_head_kernel<<<blocks, THREADS_>>>(in, anchors, out);
}

// round 7
// speedup vs baseline: 1.2179x; 1.0345x over previous
#include <cuda_runtime.h>
#include <cstdint>

// YOLOv7 P3 head: B=16, A=3, C=85/anchor, H=W=80, stride 8.
// Input:  [b, a, ch(85), h, w]   Output: [b, a*h*w, 85]
//
// R6 structure: 64-pos tile, output-layout smem, conflict-free scatter,
// per-half named barrier + TMA bulk store; 8 CTAs/SM (regs<=32).
// NEW: TMA stores carry an L2 evict_first cache policy so the write-once
// output stream drains to HBM during the kernel instead of lingering dirty
// in L2 (smaller inter-replay drain, less L2 pressure on the read stream).

#define B_       16
#define A_       3
#define C_       85
#define W_       80
#define HW_      6400
#define TILE_    64
#define THREADS_ 256
#define HALF_BYTES_ (32 * C_ * 4)   // 10880

__device__ __forceinline__ float sigm(float x) {
    float t;
    const float h = 0.5f * x;
    asm("tanh.approx.f32 %0, %1;" : "=f"(t) : "f"(h));   // 1 MUFU
    return fmaf(0.5f, t, 0.5f);
}

__global__ __launch_bounds__(THREADS_, 8)
void yolo_head_kernel(const float* __restrict__ in,
                      const float* __restrict__ anchors,
                      float* __restrict__ out)
{
    __shared__ alignas(128) float sbuf[TILE_ * C_];   // 21760 B

    const int tilesPerBA = HW_ / TILE_;      // 100
    const int bid  = blockIdx.x;
    const int ba   = bid / tilesPerBA;       // b*A + a
    const int tile = bid - ba * tilesPerBA;
    const int pos0 = tile * TILE_;
    const int a    = ba % A_;

    const float aw = __ldg(&anchors[a * 2 + 0]);
    const float ah = __ldg(&anchors[a * 2 + 1]);

    const int tid  = threadIdx.x;
    const int w    = tid >> 5;
    const int lane = tid & 31;
    const int c    = lane >> 3;              // 0..3
    const int qq   = lane & 7;               // 0..7
    const int s    = w & 1;                  // position half
    const int g0   = w >> 1;                 // 0..3
    const int p    = (s * 8 + qq) * 4;       // local position base 0..60
    const int ch0  = g0 * 4 + c;             // 0..15
    const bool tailValid = (ch0 <= 4);       // ch0+80 <= 84

    const float* tptr = in + (size_t)ba * (C_ * HW_) + pos0
                           + (size_t)ch0 * HW_ + p;

    float vv[4];

    // ---- batch 0: k = 0..2  (ch = ch0 + 16k) ----
    {
        float4 r[3];
        #pragma unroll
        for (int k = 0; k < 3; k++)
            r[k] = __ldcs(reinterpret_cast<const float4*>(tptr + (size_t)k * (16 * HW_)));

        #pragma unroll
        for (int k = 0; k < 3; k++) {
            const int ch = ch0 + 16 * k;
            vv[0] = r[k].x; vv[1] = r[k].y; vv[2] = r[k].z; vv[3] = r[k].w;

            if (k == 0 && ch < 4) {          // only warps 0,1 (g0==0), once
                if (ch == 0) {
                    const int gp = pos0 + p;
                    #pragma unroll
                    for (int j = 0; j < 4; j++)
                        vv[j] = (sigm(vv[j]) + (float)((gp + j) % W_)) * 8.0f;
                } else if (ch == 1) {
                    const int gp = pos0 + p;
                    #pragma unroll
                    for (int j = 0; j < 4; j++)
                        vv[j] = (sigm(vv[j]) + (float)((gp + j) / W_)) * 8.0f;
                } else {
                    const float sc = (ch == 2) ? aw : ah;
                    #pragma unroll
                    for (int j = 0; j < 4; j++) {
                        const float cl = fminf(fmaxf(vv[j], -16.0f), 16.0f);
                        vv[j] = __expf(cl) * sc;
                    }
                }
            } else {
                #pragma unroll
                for (int j = 0; j < 4; j++) vv[j] = sigm(vv[j]);
            }
            // bank = (20*qq + c + const) mod 32 -> conflict-free
            #pragma unroll
            for (int j = 0; j < 4; j++) sbuf[(p + j) * C_ + ch] = vv[j];
        }
    }

    // ---- batch 1: k = 3..5  (k=5 valid iff ch0 <= 4) ----
    {
        float4 r[3];
        #pragma unroll
        for (int k = 0; k < 2; k++)
            r[k] = __ldcs(reinterpret_cast<const float4*>(tptr + (size_t)(k + 3) * (16 * HW_)));
        if (tailValid)
            r[2] = __ldcs(reinterpret_cast<const float4*>(tptr + (size_t)5 * (16 * HW_)));

        #pragma unroll
        for (int k = 0; k < 3; k++) {
            if (k == 2 && !tailValid) break;
            const int ch = ch0 + 16 * (k + 3);   // >= 48: generic path
            vv[0] = r[k].x; vv[1] = r[k].y; vv[2] = r[k].z; vv[3] = r[k].w;
            #pragma unroll
            for (int j = 0; j < 4; j++) vv[j] = sigm(vv[j]);
            #pragma unroll
            for (int j = 0; j < 4; j++) sbuf[(p + j) * C_ + ch] = vv[j];
        }
    }

    // ---- per-half named barrier, then TMA half-store with evict_first policy
    if (s == 0) asm volatile("bar.sync 1, 128;" ::: "memory");  // warps 0,2,4,6
    else        asm volatile("bar.sync 2, 128;" ::: "memory");  // warps 1,3,5,7

    if (lane == 0 && w < 2) {                // warp 0 -> half 0, warp 1 -> half 1
        const int half = w;                  // == s for w<2
        float* outBase = out + ((size_t)(ba * HW_ + pos0) + half * 32) * C_;
        const float* src = sbuf + half * 32 * C_;
        uint32_t saddr;
        asm("{ .reg .u64 t; cvta.to.shared.u64 t, %1; cvt.u32.u64 %0, t; }"
            : "=r"(saddr) : "l"(src));
        uint64_t pol;
        asm("createpolicy.fractional.L2::evict_first.b64 %0, 1.0;" : "=l"(pol));
        asm volatile("fence.proxy.async.shared::cta;" ::: "memory");
        asm volatile(
            "cp.async.bulk.global.shared::cta.bulk_group.L2::cache_hint "
            "[%0], [%1], %2, %3;"
            :: "l"(outBase), "r"(saddr), "r"((uint32_t)HALF_BYTES_), "l"(pol)
            : "memory");
        asm volatile("cp.async.bulk.commit_group;" ::: "memory");
        asm volatile("cp.async.bulk.wait_group.read 0;" ::: "memory");
    }
}

extern "C" void kernel_launch(void* const* d_in, const int* in_sizes, int n_in,
                              void* d_out, int out_size) {
    const float* in      = (const float*)d_in[0];
    const float* anchors = (const float*)d_in[1];
    float* out           = (float*)d_out;

    const int blocks = B_ * A_ * (HW_ / TILE_);   // 4800
    yolo_head_kernel<<<blocks, THREADS_>>>(in, anchors, out);
}

// round 8
// speedup vs baseline: 1.2466x; 1.0236x over previous
#include <cuda_runtime.h>
#include <cstdint>

// YOLOv7 P3 head: B=16, A=3, C=85/anchor, H=W=80, stride 8.
// Input:  [b, a, ch(85), h, w]   Output: [b, a*h*w, 85]
//
// 512-thread block, 128-position tile, output-layout smem (43.5KB),
// __launch_bounds__(512,4) -> 4 CTAs x 16 warps = 64 warps/SM, regs<=32.
// Warp w: s = w&3 (position quarter), g0 = w>>2. Lane: c = lane>>3, qq = lane&7.
// STS bank = (20*qq + c + const) mod 32 -> conflict-free.
// Per-quarter named barrier (4 warps each) then 10880B TMA store with
// L2 evict_first policy.

#define B_       16
#define A_       3
#define C_       85
#define W_       80
#define HW_      6400
#define TILE_    128
#define THREADS_ 512
#define QTR_BYTES_ (32 * C_ * 4)   // 10880

__device__ __forceinline__ float sigm(float x) {
    float t;
    const float h = 0.5f * x;
    asm("tanh.approx.f32 %0, %1;" : "=f"(t) : "f"(h));   // 1 MUFU
    return fmaf(0.5f, t, 0.5f);
}

__global__ __launch_bounds__(THREADS_, 4)
void yolo_head_kernel(const float* __restrict__ in,
                      const float* __restrict__ anchors,
                      float* __restrict__ out)
{
    __shared__ alignas(128) float sbuf[TILE_ * C_];   // 43520 B

    const int tilesPerBA = HW_ / TILE_;      // 50
    const int bid  = blockIdx.x;
    const int ba   = bid / tilesPerBA;       // b*A + a
    const int tile = bid - ba * tilesPerBA;
    const int pos0 = tile * TILE_;
    const int a    = ba % A_;

    const float aw = __ldg(&anchors[a * 2 + 0]);
    const float ah = __ldg(&anchors[a * 2 + 1]);

    const int tid  = threadIdx.x;
    const int w    = tid >> 5;               // 0..15
    const int lane = tid & 31;
    const int c    = lane >> 3;              // 0..3
    const int qq   = lane & 7;               // 0..7
    const int s    = w & 3;                  // position quarter
    const int g0   = w >> 2;                 // 0..3
    const int p    = (s * 8 + qq) * 4;       // local position base 0..124
    const int ch0  = g0 * 4 + c;             // 0..15
    const bool tailValid = (ch0 <= 4);       // ch0+80 <= 84

    const float* tptr = in + (size_t)ba * (C_ * HW_) + pos0
                           + (size_t)ch0 * HW_ + p;

    float vv[4];

    // ---- batch 0: k = 0..2  (ch = ch0 + 16k) ----
    {
        float4 r[3];
        #pragma unroll
        for (int k = 0; k < 3; k++)
            r[k] = __ldcs(reinterpret_cast<const float4*>(tptr + (size_t)k * (16 * HW_)));

        #pragma unroll
        for (int k = 0; k < 3; k++) {
            const int ch = ch0 + 16 * k;
            vv[0] = r[k].x; vv[1] = r[k].y; vv[2] = r[k].z; vv[3] = r[k].w;

            if (k == 0 && ch < 4) {          // only warps 0..3 (g0==0), once
                if (ch == 0) {
                    const int gp = pos0 + p;
                    #pragma unroll
                    for (int j = 0; j < 4; j++)
                        vv[j] = (sigm(vv[j]) + (float)((gp + j) % W_)) * 8.0f;
                } else if (ch == 1) {
                    const int gp = pos0 + p;
                    #pragma unroll
                    for (int j = 0; j < 4; j++)
                        vv[j] = (sigm(vv[j]) + (float)((gp + j) / W_)) * 8.0f;
                } else {
                    const float sc = (ch == 2) ? aw : ah;
                    #pragma unroll
                    for (int j = 0; j < 4; j++) {
                        const float cl = fminf(fmaxf(vv[j], -16.0f), 16.0f);
                        vv[j] = __expf(cl) * sc;
                    }
                }
            } else {
                #pragma unroll
                for (int j = 0; j < 4; j++) vv[j] = sigm(vv[j]);
            }
            // bank = (20*qq + c + const) mod 32 -> conflict-free
            #pragma unroll
            for (int j = 0; j < 4; j++) sbuf[(p + j) * C_ + ch] = vv[j];
        }
    }

    // ---- batch 1: k = 3..5  (k=5 valid iff ch0 <= 4) ----
    {
        float4 r[3];
        #pragma unroll
        for (int k = 0; k < 2; k++)
            r[k] = __ldcs(reinterpret_cast<const float4*>(tptr + (size_t)(k + 3) * (16 * HW_)));
        if (tailValid)
            r[2] = __ldcs(reinterpret_cast<const float4*>(tptr + (size_t)5 * (16 * HW_)));

        #pragma unroll
        for (int k = 0; k < 3; k++) {
            if (k == 2 && !tailValid) break;
            const int ch = ch0 + 16 * (k + 3);   // >= 48: generic path
            vv[0] = r[k].x; vv[1] = r[k].y; vv[2] = r[k].z; vv[3] = r[k].w;
            #pragma unroll
            for (int j = 0; j < 4; j++) vv[j] = sigm(vv[j]);
            #pragma unroll
            for (int j = 0; j < 4; j++) sbuf[(p + j) * C_ + ch] = vv[j];
        }
    }

    // ---- per-quarter named barrier (4 warps = 128 threads), then TMA store
    asm volatile("bar.sync %0, 128;" :: "r"(s + 1) : "memory");

    if (lane == 0 && w < 4) {                // warp q issues quarter q (q == s)
        float* outBase = out + ((size_t)(ba * HW_ + pos0) + w * 32) * C_;
        const float* src = sbuf + w * 32 * C_;
        uint32_t saddr;
        asm("{ .reg .u64 t; cvta.to.shared.u64 t, %1; cvt.u32.u64 %0, t; }"
            : "=r"(saddr) : "l"(src));
        uint64_t pol;
        asm("createpolicy.fractional.L2::evict_first.b64 %0, 1.0;" : "=l"(pol));
        asm volatile("fence.proxy.async.shared::cta;" ::: "memory");
        asm volatile(
            "cp.async.bulk.global.shared::cta.bulk_group.L2::cache_hint "
            "[%0], [%1], %2, %3;"
            :: "l"(outBase), "r"(saddr), "r"((uint32_t)QTR_BYTES_), "l"(pol)
            : "memory");
        asm volatile("cp.async.bulk.commit_group;" ::: "memory");
        asm volatile("cp.async.bulk.wait_group.read 0;" ::: "memory");
    }
}

extern "C" void kernel_launch(void* const* d_in, const int* in_sizes, int n_in,
                              void* d_out, int out_size) {
    const float* in      = (const float*)d_in[0];
    const float* anchors = (const float*)d_in[1];
    float* out           = (float*)d_out;

    const int blocks = B_ * A_ * (HW_ / TILE_);   // 2400
    yolo_head_kernel<<<blocks, THREADS_>>>(in, anchors, out);
}